// round 8
// baseline (speedup 1.0000x reference)
#include <cuda_runtime.h>
#include <cuda_fp16.h>
#include <cstdint>

#define NTOK 8192
#define CDIM 768
#define HDIM 3072
#define H2DIM 6144
#define NEXP 16
#define NGRP 17
#define TOPK 4
#define CAP 8192

// ---------------- scratch (static __device__, no allocs) ----------------
__device__ __half g_x16[(size_t)NTOK * CDIM];                   // x fp16 [N][C]
__device__ __half g_wfc16[(size_t)NGRP * CDIM * H2DIM];         // [g][c][2H]
__device__ __half g_wpj16[(size_t)NGRP * HDIM * CDIM];          // [g][h][C]
__device__ __half g_hid[(size_t)NGRP * CAP * HDIM];             // hidden per slot
__device__ __half g_pout[(size_t)NGRP * CAP * CDIM];            // proj out per slot (fp16)
__device__ int   g_cnt[NGRP];
__device__ int   g_tok[NGRP * CAP];                             // slot -> token
__device__ int   g_tslot[NTOK * TOPK];                          // token -> slot
__device__ float g_twt[NTOK * TOPK];                            // token -> weight

// ---------------- fused gate + x fp32->fp16 convert ----------------
__global__ void gate_kernel(const float* __restrict__ x,
                            const float* __restrict__ wg,
                            const float* __restrict__ bias) {
    int warp = threadIdx.x >> 5, lane = threadIdx.x & 31;
    int n = blockIdx.x * 8 + warp;
    if (n >= NTOK) return;
    const float* xr = x + (size_t)n * CDIM;
    __half* xh = g_x16 + (size_t)n * CDIM;
    float p[NEXP];
#pragma unroll
    for (int e = 0; e < NEXP; e++) p[e] = 0.f;
    for (int c = lane; c < CDIM; c += 32) {
        float xv = xr[c];
        xh[c] = __float2half(xv);
        const float4* w4 = reinterpret_cast<const float4*>(wg + (size_t)c * NEXP);
#pragma unroll
        for (int q = 0; q < 4; q++) {
            float4 w = w4[q];
            p[4 * q + 0] += xv * w.x;
            p[4 * q + 1] += xv * w.y;
            p[4 * q + 2] += xv * w.z;
            p[4 * q + 3] += xv * w.w;
        }
    }
#pragma unroll
    for (int e = 0; e < NEXP; e++) {
        float v = p[e];
#pragma unroll
        for (int o = 16; o > 0; o >>= 1) v += __shfl_xor_sync(0xffffffffu, v, o);
        p[e] = v;
    }
    if (lane == 0) {
        float s[NEXP];
#pragma unroll
        for (int e = 0; e < NEXP; e++) s[e] = 1.f / (1.f + __expf(-(p[e] + bias[e])));
        int idx[TOPK]; float w[TOPK]; float wsum = 0.f;
        unsigned used = 0;
        for (int j = 0; j < TOPK; j++) {
            int best = 0; float bv = -1e30f;
#pragma unroll
            for (int e = 0; e < NEXP; e++) {
                bool ok = !((used >> e) & 1u);
                if (ok && s[e] > bv) { bv = s[e]; best = e; }
            }
            used |= 1u << best; idx[j] = best; w[j] = bv; wsum += bv;
        }
        float inv = 1.f / wsum;
        for (int j = 0; j < TOPK; j++) {
            int e = idx[j];
            int pos = atomicAdd(&g_cnt[e], 1);
            int slot = e * CAP + pos;
            g_tok[slot] = n;
            g_tslot[n * TOPK + j] = slot;
            g_twt[n * TOPK + j]   = w[j] * inv;
        }
        g_tok[NEXP * CAP + n] = n;
    }
}

__global__ void cvt_kernel(const float4* __restrict__ src, long n4, int target, long dstOff) {
    __half* dst = (target == 1) ? g_wfc16 : g_wpj16;
    dst += dstOff;
    long i = (long)blockIdx.x * blockDim.x + threadIdx.x;
    long stride = (long)gridDim.x * blockDim.x;
    for (; i < n4; i += stride) {
        float4 v = src[i];
        __half2* d2 = reinterpret_cast<__half2*>(dst + i * 4);
        d2[0] = __floats2half2_rn(v.x, v.y);
        d2[1] = __floats2half2_rn(v.z, v.w);
    }
}

// ---------------- GEMM machinery ----------------
__device__ __forceinline__ void cp16(uint32_t dst, const void* src, int sz) {
    asm volatile("cp.async.cg.shared.global [%0], [%1], 16, %2;\n"
                 :: "r"(dst), "l"(src), "r"(sz));
}
__device__ __forceinline__ void ldsm_x4(uint32_t& r0, uint32_t& r1, uint32_t& r2, uint32_t& r3, uint32_t a) {
    asm volatile("ldmatrix.sync.aligned.m8n8.x4.shared.b16 {%0,%1,%2,%3}, [%4];"
                 : "=r"(r0), "=r"(r1), "=r"(r2), "=r"(r3) : "r"(a));
}
__device__ __forceinline__ void ldsm_x4_t(uint32_t& r0, uint32_t& r1, uint32_t& r2, uint32_t& r3, uint32_t a) {
    asm volatile("ldmatrix.sync.aligned.m8n8.x4.trans.shared.b16 {%0,%1,%2,%3}, [%4];"
                 : "=r"(r0), "=r"(r1), "=r"(r2), "=r"(r3) : "r"(a));
}
__device__ __forceinline__ void mma16816(float* c, uint32_t a0, uint32_t a1, uint32_t a2, uint32_t a3,
                                         uint32_t b0, uint32_t b1) {
    asm volatile("mma.sync.aligned.m16n8k16.row.col.f32.f16.f16.f32 "
                 "{%0,%1,%2,%3},{%4,%5,%6,%7},{%8,%9},{%0,%1,%2,%3};"
                 : "+f"(c[0]), "+f"(c[1]), "+f"(c[2]), "+f"(c[3])
                 : "r"(a0), "r"(a1), "r"(a2), "r"(a3), "r"(b0), "r"(b1));
}
__device__ __forceinline__ float silu_f(float v) { return v * (1.f / (1.f + __expf(-v))); }

// tiles: CTA 128 rows x 128 cols, 128 threads = 4 warps (2x2), warp tile 64x64.
// Halves SMEM bytes/mma vs 8-warp 32x64 (B frag reuse x4): L1 was co-binding with tensor.
#define ASTR 72
#define BSTR 136
#define A_STAGE (128 * ASTR * 2)
#define B_STAGE (64 * BSTR * 2)
#define STAGE_BYTES (A_STAGE + B_STAGE)
#define NSTAGE 3
#define SMEM_SZ (1024 + NSTAGE * STAGE_BYTES)

// MODE 0: FC   A = gathered x16 rows [128 x C], B cols = 64 gate + 64 val of h-block, swiglu -> g_hid
// MODE 1: PROJ A = g_hid slot rows [128 x H],   B cols = 128 out channels,            -> g_pout (fp16)
template <int MODE>
__global__ void __launch_bounds__(128, 2) moe_gemm() {
    constexpr int BM = 128, BK = 64;
    constexpr int KDIM = (MODE == 0) ? CDIM : HDIM;
    constexpr int KCH = KDIM / BK;

    extern __shared__ char smem[];
    int* s_tok = (int*)smem;
    const uint32_t sb = (uint32_t)__cvta_generic_to_shared(smem);

    const int g = blockIdx.z, m0 = blockIdx.x * BM;
    const int cnt = (g == NEXP) ? NTOK : g_cnt[g];
    if (m0 >= cnt) return;

    const int tid = threadIdx.x, lane = tid & 31, warp = tid >> 5;

    if (MODE == 0) {
        int r = m0 + tid;
        s_tok[tid] = (r < cnt) ? g_tok[g * CAP + r] : -1;
    }
    __syncthreads();

    auto load_stage = [&](int st, int ch) {
        const int k0 = ch * BK;
        const uint32_t ab = sb + 1024 + st * STAGE_BYTES;
        const uint32_t bb = ab + A_STAGE;
#pragma unroll
        for (int i = 0; i < 8; i++) {                 // A: 128 rows x 128B (1024 chunks)
            int idx = tid + 128 * i;
            int row = idx >> 3, seg = idx & 7;
            uint32_t dst = ab + (uint32_t)(row * ASTR + seg * 8) * 2;
            if (MODE == 0) {
                int tok = s_tok[row];
                const __half* src = g_x16 + ((tok >= 0) ? (size_t)tok * CDIM + k0 + seg * 8 : (size_t)0);
                cp16(dst, src, tok >= 0 ? 16 : 0);
            } else {
                const __half* src = g_hid + (size_t)(g * CAP + m0 + row) * HDIM + k0 + seg * 8;
                cp16(dst, src, 16);
            }
        }
#pragma unroll
        for (int i = 0; i < 8; i++) {                 // B: 64 k-rows x 256B (1024 chunks)
            int idx = tid + 128 * i;
            int row = idx >> 4, seg = idx & 15;
            uint32_t dst = bb + (uint32_t)(row * BSTR + seg * 8) * 2;
            const __half* src;
            if (MODE == 0) {
                int j = seg * 8;
                int col = (j < 64) ? (blockIdx.y * 64 + j) : (HDIM + blockIdx.y * 64 + (j - 64));
                src = g_wfc16 + (size_t)g * CDIM * H2DIM + (size_t)(k0 + row) * H2DIM + col;
            } else {
                src = g_wpj16 + (size_t)g * HDIM * CDIM + (size_t)(k0 + row) * CDIM + blockIdx.y * 128 + seg * 8;
            }
            cp16(dst, src, 16);
        }
        asm volatile("cp.async.commit_group;\n");
    };

    float acc[4][8][4];
#pragma unroll
    for (int a = 0; a < 4; a++)
#pragma unroll
        for (int b = 0; b < 8; b++)
#pragma unroll
            for (int q = 0; q < 4; q++) acc[a][b][q] = 0.f;

    load_stage(0, 0);
    load_stage(1, 1);

    const int wm = (warp >> 1) * 64;                  // 2 warp-rows of 64
    const int wn = (warp & 1) * 32;                   // FC: 32-col slice of gate/val halves

    for (int ks = 0; ks < KCH; ks++) {
        if (ks < KCH - 1) asm volatile("cp.async.wait_group 1;\n");
        else              asm volatile("cp.async.wait_group 0;\n");
        __syncthreads();
        if (ks + 2 < KCH) load_stage((ks + 2) % NSTAGE, ks + 2);

        const int st = ks % NSTAGE;
        const uint32_t ab = sb + 1024 + st * STAGE_BYTES;
        const uint32_t bb = ab + A_STAGE;
        const uint32_t abase = ab + (uint32_t)(((wm + (lane & 15)) * ASTR + (lane >> 4) * 8) * 2);
        const uint32_t bbase = bb + (uint32_t)(((lane & 15) * BSTR + (lane >> 4) * 8) * 2);

#pragma unroll
        for (int ksub = 0; ksub < 4; ksub++) {
            uint32_t a[4][4];
#pragma unroll
            for (int mt = 0; mt < 4; mt++)
                ldsm_x4(a[mt][0], a[mt][1], a[mt][2], a[mt][3],
                        abase + (uint32_t)((mt * 16 * ASTR + ksub * 16) * 2));
#pragma unroll
            for (int half = 0; half < 2; half++) {
#pragma unroll
                for (int q = 0; q < 2; q++) {
                    int col = (MODE == 0) ? (half * 64 + wn + q * 16)
                                          : ((warp & 1) * 64 + half * 32 + q * 16);
                    uint32_t b0, b1, b2, b3;
                    ldsm_x4_t(b0, b1, b2, b3, bbase + (uint32_t)((ksub * 16 * BSTR + col) * 2));
                    int jb = half * 4 + q * 2;
#pragma unroll
                    for (int mt = 0; mt < 4; mt++) {
                        mma16816(acc[mt][jb],     a[mt][0], a[mt][1], a[mt][2], a[mt][3], b0, b1);
                        mma16816(acc[mt][jb + 1], a[mt][0], a[mt][1], a[mt][2], a[mt][3], b2, b3);
                    }
                }
            }
        }
        // no trailing __syncthreads: stage written at ks ((ks+2)%3) is distinct from
        // any stage readable between top-sync(ks) and top-sync(ks+1).
    }

    // ---------------- epilogue ----------------
    const int rq = lane >> 2, cq = (lane & 3) * 2;

    if (MODE == 0) {
#pragma unroll
        for (int mt = 0; mt < 4; mt++) {
            int r0 = wm + mt * 16 + rq;
            __half* h0 = g_hid + (size_t)(g * CAP + m0 + r0) * HDIM + blockIdx.y * 64 + wn + cq;
            __half* h1 = h0 + 8 * (size_t)HDIM;
#pragma unroll
            for (int j = 0; j < 4; j++) {
                float ga0 = acc[mt][j][0],     ga1 = acc[mt][j][1];
                float va0 = acc[mt][j + 4][0], va1 = acc[mt][j + 4][1];
                float gb0 = acc[mt][j][2],     gb1 = acc[mt][j][3];
                float vb0 = acc[mt][j + 4][2], vb1 = acc[mt][j + 4][3];
                *reinterpret_cast<__half2*>(h0 + j * 8) =
                    __floats2half2_rn(silu_f(ga0) * va0, silu_f(ga1) * va1);
                *reinterpret_cast<__half2*>(h1 + j * 8) =
                    __floats2half2_rn(silu_f(gb0) * vb0, silu_f(gb1) * vb1);
            }
        }
    } else {
        const int cw = (warp & 1) * 64;
#pragma unroll
        for (int mt = 0; mt < 4; mt++) {
            int r0 = wm + mt * 16 + rq;
            __half* o0 = g_pout + (size_t)(g * CAP + m0 + r0) * CDIM + blockIdx.y * 128 + cw + cq;
            __half* o1 = o0 + 8 * (size_t)CDIM;
#pragma unroll
            for (int j = 0; j < 8; j++) {
                *reinterpret_cast<__half2*>(o0 + j * 8) = __floats2half2_rn(acc[mt][j][0], acc[mt][j][1]);
                *reinterpret_cast<__half2*>(o1 + j * 8) = __floats2half2_rn(acc[mt][j][2], acc[mt][j][3]);
            }
        }
    }
}

// ---------------- combine: out = shared + sum_j w_j * pout[slot_j] ----------------
__global__ void combine_kernel(float* __restrict__ out) {
    int idx = blockIdx.x * 256 + threadIdx.x;       // 4 outputs per thread
    int n = idx / (CDIM / 4), c4 = idx % (CDIM / 4);
    const uint2* p = reinterpret_cast<const uint2*>(g_pout);   // 4 halves per uint2
    uint2 sv = p[((size_t)NEXP * CAP + n) * (CDIM / 4) + c4];
    float2 a01 = __half22float2(*reinterpret_cast<__half2*>(&sv.x));
    float2 a23 = __half22float2(*reinterpret_cast<__half2*>(&sv.y));
#pragma unroll
    for (int j = 0; j < TOPK; j++) {
        int slot = g_tslot[n * TOPK + j];
        float w = g_twt[n * TOPK + j];
        uint2 v = p[(size_t)slot * (CDIM / 4) + c4];
        float2 v01 = __half22float2(*reinterpret_cast<__half2*>(&v.x));
        float2 v23 = __half22float2(*reinterpret_cast<__half2*>(&v.y));
        a01.x += w * v01.x; a01.y += w * v01.y;
        a23.x += w * v23.x; a23.y += w * v23.y;
    }
    float4 r = make_float4(a01.x, a01.y, a23.x, a23.y);
    reinterpret_cast<float4*>(out)[idx] = r;
}

// ---------------- launch ----------------
extern "C" void kernel_launch(void* const* d_in, const int* in_sizes, int n_in,
                              void* d_out, int out_size) {
    const float* x   = (const float*)d_in[0];
    const float* wsf = (const float*)d_in[1];
    const float* wsp = (const float*)d_in[2];
    const float* wef = (const float*)d_in[3];
    const float* wep = (const float*)d_in[4];
    const float* wg  = (const float*)d_in[5];
    const float* eb  = (const float*)d_in[6];
    float* out = (float*)d_out;

    cudaFuncSetAttribute(moe_gemm<0>, cudaFuncAttributeMaxDynamicSharedMemorySize, SMEM_SZ);
    cudaFuncSetAttribute(moe_gemm<1>, cudaFuncAttributeMaxDynamicSharedMemorySize, SMEM_SZ);

    // device address of g_cnt (symbol shadow is host-side)
    void* cnt_ptr = nullptr;
    cudaGetSymbolAddress(&cnt_ptr, g_cnt);
    cudaMemsetAsync(cnt_ptr, 0, sizeof(int) * NGRP);

    // launch order: moe_gemm<0> is my 4th kernel => global launch idx 5 => profiled by ncu -s 5
    gate_kernel<<<NTOK / 8, 256>>>(x, wg, eb);
    cvt_kernel<<<8192, 256>>>((const float4*)wef, (long)NEXP * CDIM * H2DIM / 4, 1, 0);
    cvt_kernel<<<2048, 256>>>((const float4*)wsf, (long)CDIM * H2DIM / 4,        1, (long)NEXP * CDIM * H2DIM);

    moe_gemm<0><<<dim3(CAP / 128, HDIM / 64, NGRP), 128, SMEM_SZ>>>();                 // <-- profiled

    cvt_kernel<<<8192, 256>>>((const float4*)wep, (long)NEXP * HDIM * CDIM / 4,  2, 0);
    cvt_kernel<<<2048, 256>>>((const float4*)wsp, (long)HDIM * CDIM / 4,         2, (long)NEXP * HDIM * CDIM);

    moe_gemm<1><<<dim3(CAP / 128, CDIM / 128, NGRP), 128, SMEM_SZ>>>();

    combine_kernel<<<NTOK * CDIM / 4 / 256, 256>>>(out);
}

// round 9
// speedup vs baseline: 1.0790x; 1.0790x over previous
#include <cuda_runtime.h>
#include <cuda_fp16.h>
#include <cstdint>

#define NTOK 8192
#define CDIM 768
#define HDIM 3072
#define H2DIM 6144
#define NEXP 16
#define NGRP 17
#define TOPK 4
#define CAP 8192

// ---------------- scratch (static __device__, no allocs) ----------------
__device__ __half g_x16[(size_t)NTOK * CDIM];                   // x fp16 [N][C]
__device__ __half g_wfc16[(size_t)NGRP * CDIM * H2DIM];         // [g][c][2H]
__device__ __half g_wpj16[(size_t)NGRP * HDIM * CDIM];          // [g][h][C]
__device__ __half g_hid[(size_t)NGRP * CAP * HDIM];             // hidden per slot
__device__ __half g_pout[(size_t)NGRP * CAP * CDIM];            // proj out per slot (fp16)
__device__ int   g_cnt[NGRP];
__device__ int   g_tok[NGRP * CAP];                             // slot -> token
__device__ int   g_tslot[NTOK * TOPK];                          // token -> slot
__device__ float g_twt[NTOK * TOPK];                            // token -> weight

// ---------------- nop (launch-index pad so ncu -s 5 hits moe_gemm<1>) ----------------
__global__ void nop_kernel() {}

// ---------------- fused gate + x convert + wfc convert ----------------
// blocks [0,1024): one warp per token: convert x row to fp16, logits, top-4, lists
// blocks [1024, 7168): grid-stride fp32->fp16 convert of w_experts_fc + w_shared_fc
__global__ void gate_cvt_kernel(const float* __restrict__ x,
                                const float* __restrict__ wg,
                                const float* __restrict__ bias,
                                const float4* __restrict__ wef4,
                                const float4* __restrict__ wsf4) {
    if (blockIdx.x >= 1024) {
        const long nwe = (long)NEXP * CDIM * H2DIM / 4;
        const long ntot = nwe + (long)CDIM * H2DIM / 4;
        long i = (long)(blockIdx.x - 1024) * blockDim.x + threadIdx.x;
        const long stride = (long)(gridDim.x - 1024) * blockDim.x;
        for (; i < ntot; i += stride) {
            float4 v = (i < nwe) ? wef4[i] : wsf4[i - nwe];
            __half2* d2 = reinterpret_cast<__half2*>(g_wfc16 + i * 4);
            d2[0] = __floats2half2_rn(v.x, v.y);
            d2[1] = __floats2half2_rn(v.z, v.w);
        }
        return;
    }
    int warp = threadIdx.x >> 5, lane = threadIdx.x & 31;
    int n = blockIdx.x * 8 + warp;
    if (n >= NTOK) return;
    const float* xr = x + (size_t)n * CDIM;
    __half* xh = g_x16 + (size_t)n * CDIM;
    float p[NEXP];
#pragma unroll
    for (int e = 0; e < NEXP; e++) p[e] = 0.f;
    for (int c = lane; c < CDIM; c += 32) {
        float xv = xr[c];
        xh[c] = __float2half(xv);
        const float4* w4 = reinterpret_cast<const float4*>(wg + (size_t)c * NEXP);
#pragma unroll
        for (int q = 0; q < 4; q++) {
            float4 w = w4[q];
            p[4 * q + 0] += xv * w.x;
            p[4 * q + 1] += xv * w.y;
            p[4 * q + 2] += xv * w.z;
            p[4 * q + 3] += xv * w.w;
        }
    }
#pragma unroll
    for (int e = 0; e < NEXP; e++) {
        float v = p[e];
#pragma unroll
        for (int o = 16; o > 0; o >>= 1) v += __shfl_xor_sync(0xffffffffu, v, o);
        p[e] = v;
    }
    if (lane == 0) {
        float s[NEXP];
#pragma unroll
        for (int e = 0; e < NEXP; e++) s[e] = 1.f / (1.f + __expf(-(p[e] + bias[e])));
        int idx[TOPK]; float w[TOPK]; float wsum = 0.f;
        unsigned used = 0;
        for (int j = 0; j < TOPK; j++) {
            int best = 0; float bv = -1e30f;
#pragma unroll
            for (int e = 0; e < NEXP; e++) {
                bool ok = !((used >> e) & 1u);
                if (ok && s[e] > bv) { bv = s[e]; best = e; }
            }
            used |= 1u << best; idx[j] = best; w[j] = bv; wsum += bv;
        }
        float inv = 1.f / wsum;
        for (int j = 0; j < TOPK; j++) {
            int e = idx[j];
            int pos = atomicAdd(&g_cnt[e], 1);
            int slot = e * CAP + pos;
            g_tok[slot] = n;
            g_tslot[n * TOPK + j] = slot;
            g_twt[n * TOPK + j]   = w[j] * inv;
        }
        g_tok[NEXP * CAP + n] = n;
    }
}

// ---------------- GEMM machinery (mma.sync; tcgen05 rejected by compute_103 target) ----------------
__device__ __forceinline__ void cp16(uint32_t dst, const void* src, int sz) {
    asm volatile("cp.async.cg.shared.global [%0], [%1], 16, %2;\n"
                 :: "r"(dst), "l"(src), "r"(sz));
}
__device__ __forceinline__ void ldsm_x4(uint32_t& r0, uint32_t& r1, uint32_t& r2, uint32_t& r3, uint32_t a) {
    asm volatile("ldmatrix.sync.aligned.m8n8.x4.shared.b16 {%0,%1,%2,%3}, [%4];"
                 : "=r"(r0), "=r"(r1), "=r"(r2), "=r"(r3) : "r"(a));
}
__device__ __forceinline__ void ldsm_x4_t(uint32_t& r0, uint32_t& r1, uint32_t& r2, uint32_t& r3, uint32_t a) {
    asm volatile("ldmatrix.sync.aligned.m8n8.x4.trans.shared.b16 {%0,%1,%2,%3}, [%4];"
                 : "=r"(r0), "=r"(r1), "=r"(r2), "=r"(r3) : "r"(a));
}
__device__ __forceinline__ void mma16816(float* c, uint32_t a0, uint32_t a1, uint32_t a2, uint32_t a3,
                                         uint32_t b0, uint32_t b1) {
    asm volatile("mma.sync.aligned.m16n8k16.row.col.f32.f16.f16.f32 "
                 "{%0,%1,%2,%3},{%4,%5,%6,%7},{%8,%9},{%0,%1,%2,%3};"
                 : "+f"(c[0]), "+f"(c[1]), "+f"(c[2]), "+f"(c[3])
                 : "r"(a0), "r"(a1), "r"(a2), "r"(a3), "r"(b0), "r"(b1));
}
__device__ __forceinline__ float silu_f(float v) { return v * (1.f / (1.f + __expf(-v))); }

// tiles: CTA 128 rows x 128 cols, warp 32x64 (4x2 warps), BK=64, 3-stage, 2 CTAs/SM (R7 config)
#define ASTR 72
#define BSTR 136
#define A_STAGE (128 * ASTR * 2)
#define B_STAGE (64 * BSTR * 2)
#define STAGE_BYTES (A_STAGE + B_STAGE)
#define NSTAGE 3
#define SMEM_SZ (1024 + NSTAGE * STAGE_BYTES)

// MODE 0: FC   A = gathered x16 rows [128 x C], B cols = 64 gate + 64 val of h-block, swiglu -> g_hid
//              extra grid plane z==NGRP: fp32->fp16 convert of w_experts_proj + w_shared_proj
//              (overlaps DRAM-bound convert with the DRAM-idle GEMM wave)
// MODE 1: PROJ A = g_hid slot rows [128 x H],   B cols = 128 out channels,            -> g_pout (fp16)
template <int MODE>
__global__ void __launch_bounds__(256, 2) moe_gemm(const float4* __restrict__ cvA,
                                                   const float4* __restrict__ cvB) {
    constexpr int BM = 128, BK = 64;
    constexpr int KDIM = (MODE == 0) ? CDIM : HDIM;
    constexpr int KCH = KDIM / BK;

    if (MODE == 0 && blockIdx.z == NGRP) {
        const long nwe = (long)NEXP * HDIM * CDIM / 4;
        const long ntot = nwe + (long)HDIM * CDIM / 4;
        long i = (long)(blockIdx.y * gridDim.x + blockIdx.x) * blockDim.x + threadIdx.x;
        const long stride = (long)gridDim.x * gridDim.y * blockDim.x;
        for (; i < ntot; i += stride) {
            float4 v = (i < nwe) ? cvA[i] : cvB[i - nwe];
            __half2* d2 = reinterpret_cast<__half2*>(g_wpj16 + i * 4);
            d2[0] = __floats2half2_rn(v.x, v.y);
            d2[1] = __floats2half2_rn(v.z, v.w);
        }
        return;
    }

    extern __shared__ char smem[];
    int* s_tok = (int*)smem;
    const uint32_t sb = (uint32_t)__cvta_generic_to_shared(smem);

    const int g = blockIdx.z, m0 = blockIdx.x * BM;
    const int cnt = (g == NEXP) ? NTOK : g_cnt[g];
    if (m0 >= cnt) return;

    const int tid = threadIdx.x, lane = tid & 31, warp = tid >> 5;

    if (MODE == 0 && tid < BM) {
        int r = m0 + tid;
        s_tok[tid] = (r < cnt) ? g_tok[g * CAP + r] : -1;
    }
    __syncthreads();

    auto load_stage = [&](int st, int ch) {
        const int k0 = ch * BK;
        const uint32_t ab = sb + 1024 + st * STAGE_BYTES;
        const uint32_t bb = ab + A_STAGE;
#pragma unroll
        for (int i = 0; i < 4; i++) {                 // A: 128 rows x 128B (1024 chunks)
            int idx = tid + 256 * i;
            int row = idx >> 3, seg = idx & 7;
            uint32_t dst = ab + (uint32_t)(row * ASTR + seg * 8) * 2;
            if (MODE == 0) {
                int tok = s_tok[row];
                const __half* src = g_x16 + ((tok >= 0) ? (size_t)tok * CDIM + k0 + seg * 8 : (size_t)0);
                cp16(dst, src, tok >= 0 ? 16 : 0);
            } else {
                const __half* src = g_hid + (size_t)(g * CAP + m0 + row) * HDIM + k0 + seg * 8;
                cp16(dst, src, 16);
            }
        }
#pragma unroll
        for (int i = 0; i < 4; i++) {                 // B: 64 k-rows x 256B (1024 chunks)
            int idx = tid + 256 * i;
            int row = idx >> 4, seg = idx & 15;
            uint32_t dst = bb + (uint32_t)(row * BSTR + seg * 8) * 2;
            const __half* src;
            if (MODE == 0) {
                int j = seg * 8;
                int col = (j < 64) ? (blockIdx.y * 64 + j) : (HDIM + blockIdx.y * 64 + (j - 64));
                src = g_wfc16 + (size_t)g * CDIM * H2DIM + (size_t)(k0 + row) * H2DIM + col;
            } else {
                src = g_wpj16 + (size_t)g * HDIM * CDIM + (size_t)(k0 + row) * CDIM + blockIdx.y * 128 + seg * 8;
            }
            cp16(dst, src, 16);
        }
        asm volatile("cp.async.commit_group;\n");
    };

    float acc[2][8][4];
#pragma unroll
    for (int a = 0; a < 2; a++)
#pragma unroll
        for (int b = 0; b < 8; b++)
#pragma unroll
            for (int q = 0; q < 4; q++) acc[a][b][q] = 0.f;

    load_stage(0, 0);
    load_stage(1, 1);

    const int wm = (warp >> 1) * 32;
    const int wn = (warp & 1) * 32;

    for (int ks = 0; ks < KCH; ks++) {
        if (ks < KCH - 1) asm volatile("cp.async.wait_group 1;\n");
        else              asm volatile("cp.async.wait_group 0;\n");
        __syncthreads();
        if (ks + 2 < KCH) load_stage((ks + 2) % NSTAGE, ks + 2);

        const int st = ks % NSTAGE;
        const uint32_t ab = sb + 1024 + st * STAGE_BYTES;
        const uint32_t bb = ab + A_STAGE;
        const uint32_t abase = ab + (uint32_t)(((wm + (lane & 15)) * ASTR + (lane >> 4) * 8) * 2);
        const uint32_t bbase = bb + (uint32_t)(((lane & 15) * BSTR + (lane >> 4) * 8) * 2);

#pragma unroll
        for (int ksub = 0; ksub < 4; ksub++) {
            uint32_t a[2][4];
#pragma unroll
            for (int mt = 0; mt < 2; mt++)
                ldsm_x4(a[mt][0], a[mt][1], a[mt][2], a[mt][3],
                        abase + (uint32_t)((mt * 16 * ASTR + ksub * 16) * 2));
#pragma unroll
            for (int half = 0; half < 2; half++) {
#pragma unroll
                for (int q = 0; q < 2; q++) {
                    int col = (MODE == 0) ? (half * 64 + wn + q * 16)
                                          : ((warp & 1) * 64 + half * 32 + q * 16);
                    uint32_t b0, b1, b2, b3;
                    ldsm_x4_t(b0, b1, b2, b3, bbase + (uint32_t)((ksub * 16 * BSTR + col) * 2));
                    int jb = half * 4 + q * 2;
#pragma unroll
                    for (int mt = 0; mt < 2; mt++) {
                        mma16816(acc[mt][jb],     a[mt][0], a[mt][1], a[mt][2], a[mt][3], b0, b1);
                        mma16816(acc[mt][jb + 1], a[mt][0], a[mt][1], a[mt][2], a[mt][3], b2, b3);
                    }
                }
            }
        }
        // no trailing __syncthreads: stage written at ks ((ks+2)%3) is distinct from
        // any stage readable between top-sync(ks) and top-sync(ks+1).
    }

    // ---------------- epilogue ----------------
    const int rq = lane >> 2, cq = (lane & 3) * 2;

    if (MODE == 0) {
#pragma unroll
        for (int mt = 0; mt < 2; mt++) {
            int r0 = wm + mt * 16 + rq;
            __half* h0 = g_hid + (size_t)(g * CAP + m0 + r0) * HDIM + blockIdx.y * 64 + wn + cq;
            __half* h1 = h0 + 8 * (size_t)HDIM;
#pragma unroll
            for (int j = 0; j < 4; j++) {
                float ga0 = acc[mt][j][0],     ga1 = acc[mt][j][1];
                float va0 = acc[mt][j + 4][0], va1 = acc[mt][j + 4][1];
                float gb0 = acc[mt][j][2],     gb1 = acc[mt][j][3];
                float vb0 = acc[mt][j + 4][2], vb1 = acc[mt][j + 4][3];
                *reinterpret_cast<__half2*>(h0 + j * 8) =
                    __floats2half2_rn(silu_f(ga0) * va0, silu_f(ga1) * va1);
                *reinterpret_cast<__half2*>(h1 + j * 8) =
                    __floats2half2_rn(silu_f(gb0) * vb0, silu_f(gb1) * vb1);
            }
        }
    } else {
        const int cw = (warp & 1) * 64;
#pragma unroll
        for (int mt = 0; mt < 2; mt++) {
            int r0 = wm + mt * 16 + rq;
            __half* o0 = g_pout + (size_t)(g * CAP + m0 + r0) * CDIM + blockIdx.y * 128 + cw + cq;
            __half* o1 = o0 + 8 * (size_t)CDIM;
#pragma unroll
            for (int j = 0; j < 8; j++) {
                *reinterpret_cast<__half2*>(o0 + j * 8) = __floats2half2_rn(acc[mt][j][0], acc[mt][j][1]);
                *reinterpret_cast<__half2*>(o1 + j * 8) = __floats2half2_rn(acc[mt][j][2], acc[mt][j][3]);
            }
        }
    }
}

// ---------------- combine: out = shared + sum_j w_j * pout[slot_j] ----------------
__global__ void combine_kernel(float* __restrict__ out) {
    int idx = blockIdx.x * 256 + threadIdx.x;       // 4 outputs per thread
    int n = idx / (CDIM / 4), c4 = idx % (CDIM / 4);
    const uint2* p = reinterpret_cast<const uint2*>(g_pout);   // 4 halves per uint2
    uint2 sv = p[((size_t)NEXP * CAP + n) * (CDIM / 4) + c4];
    float2 a01 = __half22float2(*reinterpret_cast<__half2*>(&sv.x));
    float2 a23 = __half22float2(*reinterpret_cast<__half2*>(&sv.y));
#pragma unroll
    for (int j = 0; j < TOPK; j++) {
        int slot = g_tslot[n * TOPK + j];
        float w = g_twt[n * TOPK + j];
        uint2 v = p[(size_t)slot * (CDIM / 4) + c4];
        float2 v01 = __half22float2(*reinterpret_cast<__half2*>(&v.x));
        float2 v23 = __half22float2(*reinterpret_cast<__half2*>(&v.y));
        a01.x += w * v01.x; a01.y += w * v01.y;
        a23.x += w * v23.x; a23.y += w * v23.y;
    }
    float4 r = make_float4(a01.x, a01.y, a23.x, a23.y);
    reinterpret_cast<float4*>(out)[idx] = r;
}

// ---------------- launch ----------------
extern "C" void kernel_launch(void* const* d_in, const int* in_sizes, int n_in,
                              void* d_out, int out_size) {
    const float* x   = (const float*)d_in[0];
    const float* wsf = (const float*)d_in[1];
    const float* wsp = (const float*)d_in[2];
    const float* wef = (const float*)d_in[3];
    const float* wep = (const float*)d_in[4];
    const float* wg  = (const float*)d_in[5];
    const float* eb  = (const float*)d_in[6];
    float* out = (float*)d_out;

    cudaFuncSetAttribute(moe_gemm<0>, cudaFuncAttributeMaxDynamicSharedMemorySize, SMEM_SZ);
    cudaFuncSetAttribute(moe_gemm<1>, cudaFuncAttributeMaxDynamicSharedMemorySize, SMEM_SZ);

    // device address of g_cnt (the __device__ symbol itself is a host-side shadow)
    void* cnt_ptr = nullptr;
    cudaGetSymbolAddress(&cnt_ptr, g_cnt);
    cudaMemsetAsync(cnt_ptr, 0, sizeof(int) * NGRP);            // not a kernel launch

    // kernel launches (ncu counts kernels only; 2 harness pre-launches):
    nop_kernel<<<1, 32>>>();                                    // idx2 (pad)
    gate_cvt_kernel<<<7168, 256>>>(x, wg, eb,                   // idx3: gate + wfc convert
                                   (const float4*)wef, (const float4*)wsf);
    moe_gemm<0><<<dim3(CAP / 128, HDIM / 64, NGRP + 1), 256, SMEM_SZ>>>(  // idx4: FC + wpj convert
        (const float4*)wep, (const float4*)wsp);
    moe_gemm<1><<<dim3(CAP / 128, CDIM / 128, NGRP), 256, SMEM_SZ>>>(     // idx5: proj <-- profiled
        nullptr, nullptr);
    combine_kernel<<<NTOK * CDIM / 4 / 256, 256>>>(out);        // idx6
}

// round 13
// speedup vs baseline: 1.1696x; 1.0840x over previous
#include <cuda_runtime.h>
#include <cuda_fp16.h>
#include <cstdint>

#define NTOK 8192
#define CDIM 768
#define HDIM 3072
#define H2DIM 6144
#define NEXP 16
#define NGRP 17
#define TOPK 4
#define CAP 8192

// ---------------- scratch (static __device__, no allocs) ----------------
__device__ __half g_x16[(size_t)NTOK * CDIM];                   // x fp16 [N][C]
__device__ __half g_wfc16[(size_t)NGRP * CDIM * H2DIM];         // [g][c][2H]
__device__ __half g_wpj16[(size_t)NGRP * HDIM * CDIM];          // [g][h][C]
__device__ __half g_hid[(size_t)NGRP * CAP * HDIM];             // hidden per slot
__device__ __half g_pout[(size_t)NGRP * CAP * CDIM];            // proj out per slot (fp16)
__device__ int   g_cnt[NGRP];
__device__ int   g_tok[NGRP * CAP];                             // slot -> token
__device__ int   g_tslot[NTOK * TOPK];                          // token -> slot
__device__ float g_twt[NTOK * TOPK];                            // token -> weight

// ---------------- nop (launch-index pads so ncu -s 5 hits moe_gemm<0>) ----------------
__global__ void nop_kernel() {}

// ---------------- fused gate + x convert + wfc convert ----------------
// blocks [0,1024): one warp per token: convert x row to fp16, logits, top-4, lists
// blocks [1024, 7168): grid-stride fp32->fp16 convert of w_experts_fc + w_shared_fc
__global__ void gate_cvt_kernel(const float* __restrict__ x,
                                const float* __restrict__ wg,
                                const float* __restrict__ bias,
                                const float4* __restrict__ wef4,
                                const float4* __restrict__ wsf4) {
    if (blockIdx.x >= 1024) {
        const long nwe = (long)NEXP * CDIM * H2DIM / 4;
        const long ntot = nwe + (long)CDIM * H2DIM / 4;
        long i = (long)(blockIdx.x - 1024) * blockDim.x + threadIdx.x;
        const long stride = (long)(gridDim.x - 1024) * blockDim.x;
        for (; i < ntot; i += stride) {
            float4 v = (i < nwe) ? wef4[i] : wsf4[i - nwe];
            __half2* d2 = reinterpret_cast<__half2*>(g_wfc16 + i * 4);
            d2[0] = __floats2half2_rn(v.x, v.y);
            d2[1] = __floats2half2_rn(v.z, v.w);
        }
        return;
    }
    int warp = threadIdx.x >> 5, lane = threadIdx.x & 31;
    int n = blockIdx.x * 8 + warp;
    if (n >= NTOK) return;
    const float* xr = x + (size_t)n * CDIM;
    __half* xh = g_x16 + (size_t)n * CDIM;
    float p[NEXP];
#pragma unroll
    for (int e = 0; e < NEXP; e++) p[e] = 0.f;
    for (int c = lane; c < CDIM; c += 32) {
        float xv = xr[c];
        xh[c] = __float2half(xv);
        const float4* w4 = reinterpret_cast<const float4*>(wg + (size_t)c * NEXP);
#pragma unroll
        for (int q = 0; q < 4; q++) {
            float4 w = w4[q];
            p[4 * q + 0] += xv * w.x;
            p[4 * q + 1] += xv * w.y;
            p[4 * q + 2] += xv * w.z;
            p[4 * q + 3] += xv * w.w;
        }
    }
#pragma unroll
    for (int e = 0; e < NEXP; e++) {
        float v = p[e];
#pragma unroll
        for (int o = 16; o > 0; o >>= 1) v += __shfl_xor_sync(0xffffffffu, v, o);
        p[e] = v;
    }
    if (lane == 0) {
        float s[NEXP];
#pragma unroll
        for (int e = 0; e < NEXP; e++) s[e] = 1.f / (1.f + __expf(-(p[e] + bias[e])));
        int idx[TOPK]; float w[TOPK]; float wsum = 0.f;
        unsigned used = 0;
        for (int j = 0; j < TOPK; j++) {
            int best = 0; float bv = -1e30f;
#pragma unroll
            for (int e = 0; e < NEXP; e++) {
                bool ok = !((used >> e) & 1u);
                if (ok && s[e] > bv) { bv = s[e]; best = e; }
            }
            used |= 1u << best; idx[j] = best; w[j] = bv; wsum += bv;
        }
        float inv = 1.f / wsum;
        for (int j = 0; j < TOPK; j++) {
            int e = idx[j];
            int pos = atomicAdd(&g_cnt[e], 1);
            int slot = e * CAP + pos;
            g_tok[slot] = n;
            g_tslot[n * TOPK + j] = slot;
            g_twt[n * TOPK + j]   = w[j] * inv;
        }
        g_tok[NEXP * CAP + n] = n;
    }
}

// ---------------- GEMM machinery (mma.sync; tcgen05 rejected by compute_103 target) ----------------
__device__ __forceinline__ void cp16(uint32_t dst, const void* src, int sz) {
    asm volatile("cp.async.cg.shared.global [%0], [%1], 16, %2;\n"
                 :: "r"(dst), "l"(src), "r"(sz));
}
__device__ __forceinline__ void ldsm_x4(uint32_t& r0, uint32_t& r1, uint32_t& r2, uint32_t& r3, uint32_t a) {
    asm volatile("ldmatrix.sync.aligned.m8n8.x4.shared.b16 {%0,%1,%2,%3}, [%4];"
                 : "=r"(r0), "=r"(r1), "=r"(r2), "=r"(r3) : "r"(a));
}
__device__ __forceinline__ void ldsm_x4_t(uint32_t& r0, uint32_t& r1, uint32_t& r2, uint32_t& r3, uint32_t a) {
    asm volatile("ldmatrix.sync.aligned.m8n8.x4.trans.shared.b16 {%0,%1,%2,%3}, [%4];"
                 : "=r"(r0), "=r"(r1), "=r"(r2), "=r"(r3) : "r"(a));
}
__device__ __forceinline__ void mma16816(float* c, uint32_t a0, uint32_t a1, uint32_t a2, uint32_t a3,
                                         uint32_t b0, uint32_t b1) {
    asm volatile("mma.sync.aligned.m16n8k16.row.col.f32.f16.f16.f32 "
                 "{%0,%1,%2,%3},{%4,%5,%6,%7},{%8,%9},{%0,%1,%2,%3};"
                 : "+f"(c[0]), "+f"(c[1]), "+f"(c[2]), "+f"(c[3])
                 : "r"(a0), "r"(a1), "r"(a2), "r"(a3), "r"(b0), "r"(b1));
}
__device__ __forceinline__ float silu_f(float v) { return v * (1.f / (1.f + __expf(-v))); }

// ---- mbarrier helpers (sm_80/90 baseline features; legal on plain sm_103) ----
__device__ __forceinline__ void mbar_init(uint32_t a, uint32_t cnt) {
    asm volatile("mbarrier.init.shared.b64 [%0], %1;" :: "r"(a), "r"(cnt) : "memory");
}
__device__ __forceinline__ void mbar_arrive(uint32_t a) {
    asm volatile("mbarrier.arrive.shared.b64 _, [%0];" :: "r"(a) : "memory");
}
// NOTE: .noinc is load-bearing. The plain variant increments the pending count
// before the deferred arrive (net zero) and the barrier NEVER flips -> R11 hang.
// .noinc consumes one of the expected arrivals when this thread's cp.asyncs land.
__device__ __forceinline__ void cpasync_mbar_arrive(uint32_t a) {
    asm volatile("cp.async.mbarrier.arrive.noinc.shared.b64 [%0];" :: "r"(a) : "memory");
}
__device__ __forceinline__ void mbar_wait(uint32_t a, uint32_t ph) {
    asm volatile("{\n\t.reg .pred P;\n\tW%=:\n\t"
                 "mbarrier.try_wait.parity.acquire.cta.shared::cta.b64 P, [%0], %1, 0x989680;\n\t"
                 "@!P bra W%=;\n\t}"
                 :: "r"(a), "r"(ph) : "memory");
}

// tiles: CTA 128x128, warp 32x64 (4x2 warps), BK=64, 3-stage, 2 CTAs/SM.
// Mainloop sync = per-stage full/empty mbarriers (warp-skew tolerant), NOT __syncthreads:
// fast warps block only on data readiness; stragglers only delay load ISSUE 3 chunks ahead.
#define ASTR 72
#define BSTR 136
#define A_STAGE (128 * ASTR * 2)
#define B_STAGE (64 * BSTR * 2)
#define STAGE_BYTES (A_STAGE + B_STAGE)
#define NSTAGE 3
#define SMEM_SZ (1024 + NSTAGE * STAGE_BYTES)

// MODE 0: FC   A = gathered x16 rows [128 x C], B cols = 64 gate + 64 val of h-block, swiglu -> g_hid
//              extra grid plane z==NGRP: fp32->fp16 convert of w_experts_proj + w_shared_proj
// MODE 1: PROJ A = g_hid slot rows [128 x H],   B cols = 128 out channels,            -> g_pout (fp16)
template <int MODE>
__global__ void __launch_bounds__(256, 2) moe_gemm(const float4* __restrict__ cvA,
                                                   const float4* __restrict__ cvB) {
    constexpr int BM = 128, BK = 64;
    constexpr int KDIM = (MODE == 0) ? CDIM : HDIM;
    constexpr int KCH = KDIM / BK;

    if (MODE == 0 && blockIdx.z == NGRP) {
        const long nwe = (long)NEXP * HDIM * CDIM / 4;
        const long ntot = nwe + (long)HDIM * CDIM / 4;
        long i = (long)(blockIdx.y * gridDim.x + blockIdx.x) * blockDim.x + threadIdx.x;
        const long stride = (long)gridDim.x * gridDim.y * blockDim.x;
        for (; i < ntot; i += stride) {
            float4 v = (i < nwe) ? cvA[i] : cvB[i - nwe];
            __half2* d2 = reinterpret_cast<__half2*>(g_wpj16 + i * 4);
            d2[0] = __floats2half2_rn(v.x, v.y);
            d2[1] = __floats2half2_rn(v.z, v.w);
        }
        return;
    }

    extern __shared__ char smem[];
    int* s_tok = (int*)smem;
    const uint32_t sb = (uint32_t)__cvta_generic_to_shared(smem);
    const uint32_t FULLB = sb + 512, EMPTYB = sb + 512 + 8 * NSTAGE;

    const int g = blockIdx.z, m0 = blockIdx.x * BM;
    const int cnt = (g == NEXP) ? NTOK : g_cnt[g];
    if (m0 >= cnt) return;

    const int tid = threadIdx.x, lane = tid & 31, warp = tid >> 5;

    if (MODE == 0 && tid < BM) {
        int r = m0 + tid;
        s_tok[tid] = (r < cnt) ? g_tok[g * CAP + r] : -1;
    }
    if (tid == 0) {
#pragma unroll
        for (int s = 0; s < NSTAGE; s++) {
            mbar_init(FULLB + 8 * s, 256);
            mbar_init(EMPTYB + 8 * s, 256);
        }
    }
    __syncthreads();   // covers s_tok + mbarrier init; last block-wide barrier

    auto load_stage = [&](int st, int ch) {
        const int k0 = ch * BK;
        const uint32_t ab = sb + 1024 + st * STAGE_BYTES;
        const uint32_t bb = ab + A_STAGE;
#pragma unroll
        for (int i = 0; i < 4; i++) {                 // A: 128 rows x 128B (1024 chunks)
            int idx = tid + 256 * i;
            int row = idx >> 3, seg = idx & 7;
            uint32_t dst = ab + (uint32_t)(row * ASTR + seg * 8) * 2;
            if (MODE == 0) {
                int tok = s_tok[row];
                const __half* src = g_x16 + ((tok >= 0) ? (size_t)tok * CDIM + k0 + seg * 8 : (size_t)0);
                cp16(dst, src, tok >= 0 ? 16 : 0);
            } else {
                const __half* src = g_hid + (size_t)(g * CAP + m0 + row) * HDIM + k0 + seg * 8;
                cp16(dst, src, 16);
            }
        }
#pragma unroll
        for (int i = 0; i < 4; i++) {                 // B: 64 k-rows x 256B (1024 chunks)
            int idx = tid + 256 * i;
            int row = idx >> 4, seg = idx & 15;
            uint32_t dst = bb + (uint32_t)(row * BSTR + seg * 8) * 2;
            const __half* src;
            if (MODE == 0) {
                int j = seg * 8;
                int col = (j < 64) ? (blockIdx.y * 64 + j) : (HDIM + blockIdx.y * 64 + (j - 64));
                src = g_wfc16 + (size_t)g * CDIM * H2DIM + (size_t)(k0 + row) * H2DIM + col;
            } else {
                src = g_wpj16 + (size_t)g * HDIM * CDIM + (size_t)(k0 + row) * CDIM + blockIdx.y * 128 + seg * 8;
            }
            cp16(dst, src, 16);
        }
    };

    float acc[2][8][4];
#pragma unroll
    for (int a = 0; a < 2; a++)
#pragma unroll
        for (int b = 0; b < 8; b++)
#pragma unroll
            for (int q = 0; q < 4; q++) acc[a][b][q] = 0.f;

#pragma unroll
    for (int st = 0; st < NSTAGE; st++) {             // KCH >= 3 in both modes
        load_stage(st, st);
        cpasync_mbar_arrive(FULLB + 8 * st);
    }

    const int wm = (warp >> 1) * 32;
    const int wn = (warp & 1) * 32;

    for (int ks = 0; ks < KCH; ks++) {
        const int st = ks % NSTAGE;
        const uint32_t ph = (uint32_t)((ks / NSTAGE) & 1);
        mbar_wait(FULLB + 8 * st, ph);                // data ready (all 256 threads' cp.asyncs)
        __syncwarp();

        const uint32_t ab = sb + 1024 + st * STAGE_BYTES;
        const uint32_t bb = ab + A_STAGE;
        const uint32_t abase = ab + (uint32_t)(((wm + (lane & 15)) * ASTR + (lane >> 4) * 8) * 2);
        const uint32_t bbase = bb + (uint32_t)(((lane & 15) * BSTR + (lane >> 4) * 8) * 2);

#pragma unroll
        for (int ksub = 0; ksub < 4; ksub++) {
            uint32_t a[2][4];
#pragma unroll
            for (int mt = 0; mt < 2; mt++)
                ldsm_x4(a[mt][0], a[mt][1], a[mt][2], a[mt][3],
                        abase + (uint32_t)((mt * 16 * ASTR + ksub * 16) * 2));
#pragma unroll
            for (int half = 0; half < 2; half++) {
#pragma unroll
                for (int q = 0; q < 2; q++) {
                    int col = (MODE == 0) ? (half * 64 + wn + q * 16)
                                          : ((warp & 1) * 64 + half * 32 + q * 16);
                    uint32_t b0, b1, b2, b3;
                    ldsm_x4_t(b0, b1, b2, b3, bbase + (uint32_t)((ksub * 16 * BSTR + col) * 2));
                    int jb = half * 4 + q * 2;
#pragma unroll
                    for (int mt = 0; mt < 2; mt++) {
                        mma16816(acc[mt][jb],     a[mt][0], a[mt][1], a[mt][2], a[mt][3], b0, b1);
                        mma16816(acc[mt][jb + 1], a[mt][0], a[mt][1], a[mt][2], a[mt][3], b2, b3);
                    }
                }
            }
        }

        mbar_arrive(EMPTYB + 8 * st);                 // this thread done reading stage st
        if (ks + NSTAGE < KCH) {
            mbar_wait(EMPTYB + 8 * st, ph);           // all 256 threads done chunk ks
            load_stage(st, ks + NSTAGE);
            cpasync_mbar_arrive(FULLB + 8 * st);
        }
    }

    // ---------------- epilogue ----------------
    const int rq = lane >> 2, cq = (lane & 3) * 2;

    if (MODE == 0) {
#pragma unroll
        for (int mt = 0; mt < 2; mt++) {
            int r0 = wm + mt * 16 + rq;
            __half* h0 = g_hid + (size_t)(g * CAP + m0 + r0) * HDIM + blockIdx.y * 64 + wn + cq;
            __half* h1 = h0 + 8 * (size_t)HDIM;
#pragma unroll
            for (int j = 0; j < 4; j++) {
                float ga0 = acc[mt][j][0],     ga1 = acc[mt][j][1];
                float va0 = acc[mt][j + 4][0], va1 = acc[mt][j + 4][1];
                float gb0 = acc[mt][j][2],     gb1 = acc[mt][j][3];
                float vb0 = acc[mt][j + 4][2], vb1 = acc[mt][j + 4][3];
                *reinterpret_cast<__half2*>(h0 + j * 8) =
                    __floats2half2_rn(silu_f(ga0) * va0, silu_f(ga1) * va1);
                *reinterpret_cast<__half2*>(h1 + j * 8) =
                    __floats2half2_rn(silu_f(gb0) * vb0, silu_f(gb1) * vb1);
            }
        }
    } else {
        const int cw = (warp & 1) * 64;
#pragma unroll
        for (int mt = 0; mt < 2; mt++) {
            int r0 = wm + mt * 16 + rq;
            __half* o0 = g_pout + (size_t)(g * CAP + m0 + r0) * CDIM + blockIdx.y * 128 + cw + cq;
            __half* o1 = o0 + 8 * (size_t)CDIM;
#pragma unroll
            for (int j = 0; j < 8; j++) {
                *reinterpret_cast<__half2*>(o0 + j * 8) = __floats2half2_rn(acc[mt][j][0], acc[mt][j][1]);
                *reinterpret_cast<__half2*>(o1 + j * 8) = __floats2half2_rn(acc[mt][j][2], acc[mt][j][3]);
            }
        }
    }
}

// ---------------- combine: out = shared + sum_j w_j * pout[slot_j] ----------------
__global__ void combine_kernel(float* __restrict__ out) {
    int idx = blockIdx.x * 256 + threadIdx.x;       // 4 outputs per thread
    int n = idx / (CDIM / 4), c4 = idx % (CDIM / 4);
    const uint2* p = reinterpret_cast<const uint2*>(g_pout);   // 4 halves per uint2
    uint2 sv = p[((size_t)NEXP * CAP + n) * (CDIM / 4) + c4];
    float2 a01 = __half22float2(*reinterpret_cast<__half2*>(&sv.x));
    float2 a23 = __half22float2(*reinterpret_cast<__half2*>(&sv.y));
#pragma unroll
    for (int j = 0; j < TOPK; j++) {
        int slot = g_tslot[n * TOPK + j];
        float w = g_twt[n * TOPK + j];
        uint2 v = p[(size_t)slot * (CDIM / 4) + c4];
        float2 v01 = __half22float2(*reinterpret_cast<__half2*>(&v.x));
        float2 v23 = __half22float2(*reinterpret_cast<__half2*>(&v.y));
        a01.x += w * v01.x; a01.y += w * v01.y;
        a23.x += w * v23.x; a23.y += w * v23.y;
    }
    float4 r = make_float4(a01.x, a01.y, a23.x, a23.y);
    reinterpret_cast<float4*>(out)[idx] = r;
}

// ---------------- launch ----------------
extern "C" void kernel_launch(void* const* d_in, const int* in_sizes, int n_in,
                              void* d_out, int out_size) {
    const float* x   = (const float*)d_in[0];
    const float* wsf = (const float*)d_in[1];
    const float* wsp = (const float*)d_in[2];
    const float* wef = (const float*)d_in[3];
    const float* wep = (const float*)d_in[4];
    const float* wg  = (const float*)d_in[5];
    const float* eb  = (const float*)d_in[6];
    float* out = (float*)d_out;

    cudaFuncSetAttribute(moe_gemm<0>, cudaFuncAttributeMaxDynamicSharedMemorySize, SMEM_SZ);
    cudaFuncSetAttribute(moe_gemm<1>, cudaFuncAttributeMaxDynamicSharedMemorySize, SMEM_SZ);

    // device address of g_cnt (the __device__ symbol itself is a host-side shadow)
    void* cnt_ptr = nullptr;
    cudaGetSymbolAddress(&cnt_ptr, g_cnt);
    cudaMemsetAsync(cnt_ptr, 0, sizeof(int) * NGRP);            // not a kernel launch

    // kernel launches (2 harness pre-launches; 2 nops pad so ncu -s 5 profiles moe_gemm<0>)
    nop_kernel<<<1, 32>>>();                                    // idx2
    nop_kernel<<<1, 32>>>();                                    // idx3
    gate_cvt_kernel<<<7168, 256>>>(x, wg, eb,                   // idx4: gate + wfc convert
                                   (const float4*)wef, (const float4*)wsf);
    moe_gemm<0><<<dim3(CAP / 128, HDIM / 64, NGRP + 1), 256, SMEM_SZ>>>(  // idx5: FC <-- profiled
        (const float4*)wep, (const float4*)wsp);
    moe_gemm<1><<<dim3(CAP / 128, CDIM / 128, NGRP), 256, SMEM_SZ>>>(     // idx6: proj
        nullptr, nullptr);
    combine_kernel<<<NTOK * CDIM / 4 / 256, 256>>>(out);        // idx7
}